// round 5
// baseline (speedup 1.0000x reference)
#include <cuda_runtime.h>
#include <math.h>

// Problem constants
#define BB 8
#define LL 2048
#define DD 512
#define KK 4096
#define NROWS (BB * LL)          // 16384
#define QELEMS (NROWS * DD)      // 8388608
#define DECAYF 0.99f
#define EPSF 1e-5f

// ---------------- scratch (device globals: no allocation allowed) ----------------
__device__ float g_c2[KK];            // ||c_k||^2
__device__ float g_x2[NROWS];         // ||x_i||^2
__device__ float g_counts[KK];        // cluster_counts (zeroed each launch)
__device__ float g_dw[KK * DD];       // scatter-add of x rows (zeroed each launch)
__device__ float g_avgc[KK];          // avg_cluster
__device__ float g_cbnew[KK * DD];    // codebook_new
__device__ float g_scal[4];           // [0]=N, [1]=loss sum, [2]=bias
__device__ int   g_idx[NROWS];        // argmin indices

// ---------------- packed fp32x2 helpers (Blackwell FFMA2 pipe) ----------------
__device__ __forceinline__ unsigned long long pack2_bcast(float v) {
    unsigned long long r;
    asm("mov.b64 %0, {%1, %1};" : "=l"(r) : "f"(v));
    return r;
}
__device__ __forceinline__ void unpack2(unsigned long long v, float& lo, float& hi) {
    asm("mov.b64 {%0, %1}, %2;" : "=f"(lo), "=f"(hi) : "l"(v));
}
__device__ __forceinline__ unsigned long long ffma2(unsigned long long a,
                                                    unsigned long long b,
                                                    unsigned long long c) {
    unsigned long long d;
    asm("fma.rn.f32x2 %0, %1, %2, %3;" : "=l"(d) : "l"(a), "l"(b), "l"(c));
    return d;
}

// ---------------- K0: zero scratch (graph-replay safe) ----------------
__global__ void zero_kernel() {
    const int total = KK * DD + KK + 2;
    for (int i = blockIdx.x * blockDim.x + threadIdx.x; i < total;
         i += gridDim.x * blockDim.x) {
        if (i < KK * DD)            g_dw[i] = 0.0f;
        else if (i < KK * DD + KK)  g_counts[i - KK * DD] = 0.0f;
        else                        g_scal[i - KK * DD - KK] = 0.0f;
    }
}

// ---------------- K1: row sums of squares (c2 for codebook, x2 for x) ----------------
__global__ void sumsq_kernel(const float* __restrict__ cb, const float* __restrict__ x) {
    int row  = (blockIdx.x * blockDim.x + threadIdx.x) >> 5;
    int lane = threadIdx.x & 31;
    if (row >= KK + NROWS) return;
    const float* p = (row < KK) ? (cb + (size_t)row * DD)
                                : (x + (size_t)(row - KK) * DD);
    float s = 0.0f;
    #pragma unroll
    for (int d = lane; d < DD; d += 32) { float v = p[d]; s += v * v; }
    #pragma unroll
    for (int o = 16; o > 0; o >>= 1) s += __shfl_xor_sync(0xFFFFFFFFu, s, o);
    if (lane == 0) {
        if (row < KK) g_c2[row] = s;
        else          g_x2[row - KK] = s;
    }
}

// ---------------- K2: fused GEMM + argmin ----------------
// Block: 128 x-rows, loops over all 4096 codes in 128-wide tiles, BK=16.
// 256 threads = 16x16; each thread owns an 8x8 micro-tile, packed as 8x4 f32x2.
// cs-tile operand pairs are read via LDS.64 so they land pre-packed for FFMA2.
__global__ __launch_bounds__(256) void argmin_kernel(const float* __restrict__ x,
                                                     const float* __restrict__ cb) {
    __shared__ float xs[16][132];   // [k][m], padded; 528B rows keep 16B alignment
    __shared__ float cs[16][132];   // [k][n]
    __shared__ float rbv[128][17];
    __shared__ int   rbi[128][17];

    const int tid = threadIdx.x;
    const int tx = tid & 15, ty = tid >> 4;
    const int m0 = blockIdx.x * 128;

    float best[8];
    int   bidx[8];
    #pragma unroll
    for (int i = 0; i < 8; i++) { best[i] = 3.4e38f; bidx[i] = 0; }

    float x2v[8];
    #pragma unroll
    for (int i = 0; i < 8; i++) x2v[i] = g_x2[m0 + ty * 8 + i];

    for (int n0 = 0; n0 < KK; n0 += 128) {
        unsigned long long acc2[8][4];
        #pragma unroll
        for (int i = 0; i < 8; i++)
            #pragma unroll
            for (int j = 0; j < 4; j++) acc2[i][j] = 0ull;

        for (int k0 = 0; k0 < DD; k0 += 16) {
            // Each thread loads 2 float4 from x-tile and 2 from c-tile.
            #pragma unroll
            for (int s = 0; s < 2; s++) {
                int q   = tid * 2 + s;          // 0..511
                int row = q >> 2;               // 0..127
                int kq  = (q & 3) << 2;         // 0,4,8,12
                float4 vx = *(const float4*)(x  + (size_t)(m0 + row) * DD + k0 + kq);
                float4 vc = *(const float4*)(cb + (size_t)(n0 + row) * DD + k0 + kq);
                xs[kq + 0][row] = vx.x; xs[kq + 1][row] = vx.y;
                xs[kq + 2][row] = vx.z; xs[kq + 3][row] = vx.w;
                cs[kq + 0][row] = vc.x; cs[kq + 1][row] = vc.y;
                cs[kq + 2][row] = vc.z; cs[kq + 3][row] = vc.w;
            }
            __syncthreads();
            #pragma unroll
            for (int kk = 0; kk < 16; kk++) {
                const float4* ar = (const float4*)&xs[kk][ty * 8];
                // c-pairs read directly as packed 64-bit values (LDS.64/LDS.128)
                const unsigned long long* br =
                    (const unsigned long long*)&cs[kk][tx * 8];
                float4 a0 = ar[0], a1 = ar[1];
                unsigned long long bp[4] = { br[0], br[1], br[2], br[3] };
                float av[8] = { a0.x, a0.y, a0.z, a0.w, a1.x, a1.y, a1.z, a1.w };
                #pragma unroll
                for (int i = 0; i < 8; i++) {
                    unsigned long long ap = pack2_bcast(av[i]);
                    #pragma unroll
                    for (int j = 0; j < 4; j++)
                        acc2[i][j] = ffma2(ap, bp[j], acc2[i][j]);
                }
            }
            __syncthreads();
        }

        // Epilogue: d2 = (x2 - 2*xc) + c2, running argmin (n ascending => first-min)
        float c2v[8];
        #pragma unroll
        for (int j = 0; j < 8; j++) c2v[j] = g_c2[n0 + tx * 8 + j];
        #pragma unroll
        for (int i = 0; i < 8; i++) {
            #pragma unroll
            for (int j2 = 0; j2 < 4; j2++) {
                float lo, hi;
                unpack2(acc2[i][j2], lo, hi);
                int nl = n0 + tx * 8 + j2 * 2;
                float d0 = (x2v[i] - 2.0f * lo) + c2v[j2 * 2];
                float d1 = (x2v[i] - 2.0f * hi) + c2v[j2 * 2 + 1];
                if (d0 < best[i]) { best[i] = d0; bidx[i] = nl; }
                if (d1 < best[i]) { best[i] = d1; bidx[i] = nl + 1; }
            }
        }
    }

    // Cross-thread argmin over the 16 tx lanes sharing each m-row.
    #pragma unroll
    for (int i = 0; i < 8; i++) {
        rbv[ty * 8 + i][tx] = best[i];
        rbi[ty * 8 + i][tx] = bidx[i];
    }
    __syncthreads();
    if (tid < 128) {
        float bv = rbv[tid][0];
        int   bi = rbi[tid][0];
        #pragma unroll
        for (int t2 = 1; t2 < 16; t2++) {
            float v = rbv[tid][t2];
            int  id = rbi[tid][t2];
            if (v < bv || (v == bv && id < bi)) { bv = v; bi = id; }
        }
        g_idx[m0 + tid] = bi;
    }
}

// ---------------- K3: scatter-add counts and dw ----------------
__global__ void scatter_kernel(const float* __restrict__ x) {
    int w    = (blockIdx.x * blockDim.x + threadIdx.x) >> 5;
    int lane = threadIdx.x & 31;
    if (w >= NROWS) return;
    int idx = g_idx[w];
    if (lane == 0) atomicAdd(&g_counts[idx], 1.0f);
    const float* xr = x + (size_t)w * DD;
    float* dwr = g_dw + (size_t)idx * DD;
    #pragma unroll
    for (int d = lane; d < DD; d += 32) atomicAdd(&dwr[d], xr[d]);
}

// ---------------- K4: EMA cluster stats, bias, N ----------------
__global__ void stats_kernel(const float* __restrict__ hidden_cluster,
                             const float* __restrict__ count) {
    __shared__ float sred[1024];
    int t = threadIdx.x;
    float cnt1 = count[0] + 1.0f;
    float bias = 1.0f - exp2f(cnt1 * log2f(DECAYF));
    float local = 0.0f;
    for (int k = t; k < KK; k += 1024) {
        float hc = hidden_cluster[k] * DECAYF + (1.0f - DECAYF) * g_counts[k];
        float a  = hc / bias;
        g_avgc[k] = a;
        local += a;
    }
    sred[t] = local;
    __syncthreads();
    for (int s = 512; s > 0; s >>= 1) {
        if (t < s) sred[t] += sred[t + s];
        __syncthreads();
    }
    if (t == 0) { g_scal[0] = sred[0]; g_scal[2] = bias; }
}

// ---------------- K5: codebook_new ----------------
__global__ void cbnew_kernel(const float* __restrict__ hidden_dw) {
    int i = blockIdx.x * blockDim.x + threadIdx.x;  // grid covers KK*DD exactly
    if (i >= KK * DD) return;
    float N    = g_scal[0];
    float bias = g_scal[2];
    int   k    = i >> 9;
    float avgdw = (hidden_dw[i] * DECAYF + (1.0f - DECAYF) * g_dw[i]) / bias;
    float cc    = (g_avgc[k] + EPSF) / (N + 4096.0f * EPSF) * N;
    g_cbnew[i]  = avgdw / cc;
}

// ---------------- K6: gather quantized + loss partials + indices ----------------
__global__ void output_kernel(const float* __restrict__ x, float* __restrict__ out,
                              int out_size) {
    __shared__ float sred[128];
    int r = blockIdx.x;
    int t = threadIdx.x;
    int idx = g_idx[r];
    const float4* q4 = (const float4*)(g_cbnew + (size_t)idx * DD);
    const float4* x4 = (const float4*)(x + (size_t)r * DD);
    float4*       o4 = (float4*)(out + (size_t)r * DD);
    float4 q  = q4[t];
    float4 xv = x4[t];
    float4 o;
    o.x = xv.x + (q.x - xv.x);
    o.y = xv.y + (q.y - xv.y);
    o.z = xv.z + (q.z - xv.z);
    o.w = xv.w + (q.w - xv.w);
    float dx = xv.x - o.x, dy = xv.y - o.y, dz = xv.z - o.z, dw = xv.w - o.w;
    float local = dx * dx + dy * dy + dz * dz + dw * dw;
    o4[t] = o;
    sred[t] = local;
    __syncthreads();
    for (int s = 64; s > 0; s >>= 1) {
        if (t < s) sred[t] += sred[t + s];
        __syncthreads();
    }
    if (t == 0) {
        atomicAdd(&g_scal[1], sred[0]);
        if (out_size >= QELEMS + 1 + NROWS)
            out[QELEMS + 1 + r] = (float)idx;
    }
}

// ---------------- K7: finalize loss ----------------
__global__ void finalize_kernel(float* __restrict__ out, int out_size) {
    if (out_size > QELEMS)
        out[QELEMS] = 0.5f * (g_scal[1] / (float)QELEMS);
}

// ---------------- launch ----------------
extern "C" void kernel_launch(void* const* d_in, const int* in_sizes, int n_in,
                              void* d_out, int out_size) {
    const float* x              = (const float*)d_in[0];
    const float* codebook       = (const float*)d_in[1];
    const float* hidden_cluster = (const float*)d_in[2];
    const float* hidden_dw      = (const float*)d_in[3];
    const float* count          = (const float*)d_in[4];
    float* out = (float*)d_out;

    zero_kernel<<<2048, 1024>>>();
    sumsq_kernel<<<(KK + NROWS) / 8, 256>>>(codebook, x);
    argmin_kernel<<<NROWS / 128, 256>>>(x, codebook);
    scatter_kernel<<<NROWS / 8, 256>>>(x);
    stats_kernel<<<1, 1024>>>(hidden_cluster, count);
    cbnew_kernel<<<(KK * DD) / 512, 512>>>(hidden_dw);
    output_kernel<<<NROWS, 128>>>(x, out, out_size);
    finalize_kernel<<<1, 1>>>(out, out_size);
}

// round 7
// speedup vs baseline: 1.0887x; 1.0887x over previous
#include <cuda_runtime.h>
#include <math.h>

// Problem constants
#define BB 8
#define LL 2048
#define DD 512
#define KK 4096
#define NROWS (BB * LL)          // 16384
#define QELEMS (NROWS * DD)      // 8388608
#define DECAYF 0.99f
#define EPSF 1e-5f
#define NHALF (KK / 2)           // 2048 codes per block half

// ---------------- scratch (device globals: no allocation allowed) ----------------
__device__ float g_c2[KK];            // ||c_k||^2
__device__ float g_x2[NROWS];         // ||x_i||^2
__device__ float g_counts[KK];        // cluster_counts (zeroed each launch)
__device__ float g_dw[KK * DD];       // scatter-add of x rows (zeroed each launch)
__device__ float g_avgc[KK];          // avg_cluster
__device__ float g_cbnew[KK * DD];    // codebook_new
__device__ float g_scal[4];           // [0]=N, [1]=loss sum, [2]=bias
__device__ int   g_idx[NROWS];        // final argmin indices
__device__ float g_pbv[2 * NROWS];    // per-half best distance
__device__ int   g_pbi[2 * NROWS];    // per-half best index

// ---------------- packed fp32x2 helpers (Blackwell FFMA2 pipe) ----------------
__device__ __forceinline__ unsigned long long pack2_bcast(float v) {
    unsigned long long r;
    asm("mov.b64 %0, {%1, %1};" : "=l"(r) : "f"(v));
    return r;
}
__device__ __forceinline__ void unpack2(unsigned long long v, float& lo, float& hi) {
    asm("mov.b64 {%0, %1}, %2;" : "=f"(lo), "=f"(hi) : "l"(v));
}
__device__ __forceinline__ unsigned long long ffma2(unsigned long long a,
                                                    unsigned long long b,
                                                    unsigned long long c) {
    unsigned long long d;
    asm("fma.rn.f32x2 %0, %1, %2, %3;" : "=l"(d) : "l"(a), "l"(b), "l"(c));
    return d;
}

// ---------------- K0: zero scratch (graph-replay safe) ----------------
__global__ void zero_kernel() {
    const int total = KK * DD + KK + 2;
    for (int i = blockIdx.x * blockDim.x + threadIdx.x; i < total;
         i += gridDim.x * blockDim.x) {
        if (i < KK * DD)            g_dw[i] = 0.0f;
        else if (i < KK * DD + KK)  g_counts[i - KK * DD] = 0.0f;
        else                        g_scal[i - KK * DD - KK] = 0.0f;
    }
}

// ---------------- K1: row sums of squares (c2 for codebook, x2 for x) ----------------
__global__ void sumsq_kernel(const float* __restrict__ cb, const float* __restrict__ x) {
    int row  = (blockIdx.x * blockDim.x + threadIdx.x) >> 5;
    int lane = threadIdx.x & 31;
    if (row >= KK + NROWS) return;
    const float* p = (row < KK) ? (cb + (size_t)row * DD)
                                : (x + (size_t)(row - KK) * DD);
    float s = 0.0f;
    #pragma unroll
    for (int d = lane; d < DD; d += 32) { float v = p[d]; s += v * v; }
    #pragma unroll
    for (int o = 16; o > 0; o >>= 1) s += __shfl_xor_sync(0xFFFFFFFFu, s, o);
    if (lane == 0) {
        if (row < KK) g_c2[row] = s;
        else          g_x2[row - KK] = s;
    }
}

// ---------------- K2: fused GEMM + argmin (split over code halves) ----------------
// grid = (128 m-tiles, 2 halves). Block: 128 x-rows x 2048 codes, BK=16.
// 256 threads = 16x16; each thread owns an 8x8 micro-tile, packed as 8x4 f32x2.
// __launch_bounds__(256,2): 2 CTAs/SM -> 4 warps/SMSP to hide barrier drains.
__global__ __launch_bounds__(256, 2) void argmin_kernel(const float* __restrict__ x,
                                                        const float* __restrict__ cb) {
    __shared__ float xs[16][132];   // [k][m], padded; rows 16B-aligned
    __shared__ float cs[16][132];   // [k][n]
    __shared__ float rbv[128][17];
    __shared__ int   rbi[128][17];

    const int tid = threadIdx.x;
    const int tx = tid & 15, ty = tid >> 4;
    const int m0 = blockIdx.x * 128;
    const int half = blockIdx.y;
    const int nbase = half * NHALF;

    float best[8];
    int   bidx[8];
    #pragma unroll
    for (int i = 0; i < 8; i++) { best[i] = 3.4e38f; bidx[i] = 0; }

    float x2v[8];
    #pragma unroll
    for (int i = 0; i < 8; i++) x2v[i] = g_x2[m0 + ty * 8 + i];

    for (int n0 = nbase; n0 < nbase + NHALF; n0 += 128) {
        unsigned long long acc2[8][4];
        #pragma unroll
        for (int i = 0; i < 8; i++)
            #pragma unroll
            for (int j = 0; j < 4; j++) acc2[i][j] = 0ull;

        for (int k0 = 0; k0 < DD; k0 += 16) {
            // Each thread loads 2 float4 from x-tile and 2 from c-tile.
            #pragma unroll
            for (int s = 0; s < 2; s++) {
                int q   = tid * 2 + s;          // 0..511
                int row = q >> 2;               // 0..127
                int kq  = (q & 3) << 2;         // 0,4,8,12
                float4 vx = *(const float4*)(x  + (size_t)(m0 + row) * DD + k0 + kq);
                float4 vc = *(const float4*)(cb + (size_t)(n0 + row) * DD + k0 + kq);
                xs[kq + 0][row] = vx.x; xs[kq + 1][row] = vx.y;
                xs[kq + 2][row] = vx.z; xs[kq + 3][row] = vx.w;
                cs[kq + 0][row] = vc.x; cs[kq + 1][row] = vc.y;
                cs[kq + 2][row] = vc.z; cs[kq + 3][row] = vc.w;
            }
            __syncthreads();
            #pragma unroll
            for (int kk = 0; kk < 16; kk++) {
                const float4* ar = (const float4*)&xs[kk][ty * 8];
                // c-pairs read directly as packed 64-bit values (LDS.128)
                const unsigned long long* br =
                    (const unsigned long long*)&cs[kk][tx * 8];
                float4 a0 = ar[0], a1 = ar[1];
                unsigned long long bp[4] = { br[0], br[1], br[2], br[3] };
                float av[8] = { a0.x, a0.y, a0.z, a0.w, a1.x, a1.y, a1.z, a1.w };
                #pragma unroll
                for (int i = 0; i < 8; i++) {
                    unsigned long long ap = pack2_bcast(av[i]);
                    #pragma unroll
                    for (int j = 0; j < 4; j++)
                        acc2[i][j] = ffma2(ap, bp[j], acc2[i][j]);
                }
            }
            __syncthreads();
        }

        // Epilogue: d2 = (x2 - 2*xc) + c2, running argmin (n ascending => first-min)
        float c2v[8];
        #pragma unroll
        for (int j = 0; j < 8; j++) c2v[j] = g_c2[n0 + tx * 8 + j];
        #pragma unroll
        for (int i = 0; i < 8; i++) {
            #pragma unroll
            for (int j2 = 0; j2 < 4; j2++) {
                float lo, hi;
                unpack2(acc2[i][j2], lo, hi);
                int nl = n0 + tx * 8 + j2 * 2;
                float d0 = (x2v[i] - 2.0f * lo) + c2v[j2 * 2];
                float d1 = (x2v[i] - 2.0f * hi) + c2v[j2 * 2 + 1];
                if (d0 < best[i]) { best[i] = d0; bidx[i] = nl; }
                if (d1 < best[i]) { best[i] = d1; bidx[i] = nl + 1; }
            }
        }
    }

    // Cross-thread argmin over the 16 tx lanes sharing each m-row.
    #pragma unroll
    for (int i = 0; i < 8; i++) {
        rbv[ty * 8 + i][tx] = best[i];
        rbi[ty * 8 + i][tx] = bidx[i];
    }
    __syncthreads();
    if (tid < 128) {
        float bv = rbv[tid][0];
        int   bi = rbi[tid][0];
        #pragma unroll
        for (int t2 = 1; t2 < 16; t2++) {
            float v = rbv[tid][t2];
            int  id = rbi[tid][t2];
            if (v < bv || (v == bv && id < bi)) { bv = v; bi = id; }
        }
        g_pbv[half * NROWS + m0 + tid] = bv;
        g_pbi[half * NROWS + m0 + tid] = bi;
    }
}

// ---------------- K2b: merge the two code-halves (tie -> lower half/index) ----------------
__global__ void reduce_kernel() {
    int r = blockIdx.x * blockDim.x + threadIdx.x;
    if (r >= NROWS) return;
    float v0 = g_pbv[r], v1 = g_pbv[NROWS + r];
    int   i0 = g_pbi[r], i1 = g_pbi[NROWS + r];
    // half-0 indices are strictly lower, so ties keep i0 (first-min semantics)
    g_idx[r] = (v1 < v0) ? i1 : i0;
}

// ---------------- K3: scatter-add counts and dw ----------------
__global__ void scatter_kernel(const float* __restrict__ x) {
    int w    = (blockIdx.x * blockDim.x + threadIdx.x) >> 5;
    int lane = threadIdx.x & 31;
    if (w >= NROWS) return;
    int idx = g_idx[w];
    if (lane == 0) atomicAdd(&g_counts[idx], 1.0f);
    const float* xr = x + (size_t)w * DD;
    float* dwr = g_dw + (size_t)idx * DD;
    #pragma unroll
    for (int d = lane; d < DD; d += 32) atomicAdd(&dwr[d], xr[d]);
}

// ---------------- K4: EMA cluster stats, bias, N ----------------
__global__ void stats_kernel(const float* __restrict__ hidden_cluster,
                             const float* __restrict__ count) {
    __shared__ float sred[1024];
    int t = threadIdx.x;
    float cnt1 = count[0] + 1.0f;
    float bias = 1.0f - exp2f(cnt1 * log2f(DECAYF));
    float local = 0.0f;
    for (int k = t; k < KK; k += 1024) {
        float hc = hidden_cluster[k] * DECAYF + (1.0f - DECAYF) * g_counts[k];
        float a  = hc / bias;
        g_avgc[k] = a;
        local += a;
    }
    sred[t] = local;
    __syncthreads();
    for (int s = 512; s > 0; s >>= 1) {
        if (t < s) sred[t] += sred[t + s];
        __syncthreads();
    }
    if (t == 0) { g_scal[0] = sred[0]; g_scal[2] = bias; }
}

// ---------------- K5: codebook_new ----------------
__global__ void cbnew_kernel(const float* __restrict__ hidden_dw) {
    int i = blockIdx.x * blockDim.x + threadIdx.x;  // grid covers KK*DD exactly
    if (i >= KK * DD) return;
    float N    = g_scal[0];
    float bias = g_scal[2];
    int   k    = i >> 9;
    float avgdw = (hidden_dw[i] * DECAYF + (1.0f - DECAYF) * g_dw[i]) / bias;
    float cc    = (g_avgc[k] + EPSF) / (N + 4096.0f * EPSF) * N;
    g_cbnew[i]  = avgdw / cc;
}

// ---------------- K6: gather quantized + loss partials + indices ----------------
__global__ void output_kernel(const float* __restrict__ x, float* __restrict__ out,
                              int out_size) {
    __shared__ float sred[128];
    int r = blockIdx.x;
    int t = threadIdx.x;
    int idx = g_idx[r];
    const float4* q4 = (const float4*)(g_cbnew + (size_t)idx * DD);
    const float4* x4 = (const float4*)(x + (size_t)r * DD);
    float4*       o4 = (float4*)(out + (size_t)r * DD);
    float4 q  = q4[t];
    float4 xv = x4[t];
    float4 o;
    o.x = xv.x + (q.x - xv.x);
    o.y = xv.y + (q.y - xv.y);
    o.z = xv.z + (q.z - xv.z);
    o.w = xv.w + (q.w - xv.w);
    float dx = xv.x - o.x, dy = xv.y - o.y, dz = xv.z - o.z, dw = xv.w - o.w;
    float local = dx * dx + dy * dy + dz * dz + dw * dw;
    o4[t] = o;
    sred[t] = local;
    __syncthreads();
    for (int s = 64; s > 0; s >>= 1) {
        if (t < s) sred[t] += sred[t + s];
        __syncthreads();
    }
    if (t == 0) {
        atomicAdd(&g_scal[1], sred[0]);
        if (out_size >= QELEMS + 1 + NROWS)
            out[QELEMS + 1 + r] = (float)idx;
    }
}

// ---------------- K7: finalize loss ----------------
__global__ void finalize_kernel(float* __restrict__ out, int out_size) {
    if (out_size > QELEMS)
        out[QELEMS] = 0.5f * (g_scal[1] / (float)QELEMS);
}

// ---------------- launch ----------------
extern "C" void kernel_launch(void* const* d_in, const int* in_sizes, int n_in,
                              void* d_out, int out_size) {
    const float* x              = (const float*)d_in[0];
    const float* codebook       = (const float*)d_in[1];
    const float* hidden_cluster = (const float*)d_in[2];
    const float* hidden_dw      = (const float*)d_in[3];
    const float* count          = (const float*)d_in[4];
    float* out = (float*)d_out;

    zero_kernel<<<2048, 1024>>>();
    sumsq_kernel<<<(KK + NROWS) / 8, 256>>>(codebook, x);
    argmin_kernel<<<dim3(NROWS / 128, 2), 256>>>(x, codebook);
    reduce_kernel<<<NROWS / 256, 256>>>();
    scatter_kernel<<<NROWS / 8, 256>>>(x);
    stats_kernel<<<1, 1024>>>(hidden_cluster, count);
    cbnew_kernel<<<(KK * DD) / 512, 512>>>(hidden_dw);
    output_kernel<<<NROWS, 128>>>(x, out, out_size);
    finalize_kernel<<<1, 1>>>(out, out_size);
}

// round 10
// speedup vs baseline: 1.0907x; 1.0018x over previous
#include <cuda_runtime.h>
#include <math.h>

// Problem constants
#define BB 8
#define LL 2048
#define DD 512
#define KK 4096
#define NROWS (BB * LL)          // 16384
#define QELEMS (NROWS * DD)      // 8388608
#define DECAYF 0.99f
#define EPSF 1e-5f
#define NHALF (KK / 2)           // 2048 codes per block half

// ---------------- scratch (device globals: no allocation allowed) ----------------
__device__ float g_c2[KK];            // ||c_k||^2
__device__ float g_x2[NROWS];         // ||x_i||^2
__device__ float g_counts[KK];        // cluster_counts (zeroed each launch)
__device__ float g_dw[KK * DD];       // scatter-add of x rows (zeroed each launch)
__device__ float g_avgc[KK];          // avg_cluster
__device__ float g_cbnew[KK * DD];    // codebook_new
__device__ float g_scal[4];           // [0]=N, [1]=loss sum, [2]=bias
__device__ int   g_idx[NROWS];        // final argmin indices
__device__ float g_pbv[2 * NROWS];    // per-half best distance
__device__ int   g_pbi[2 * NROWS];    // per-half best index

// ---------------- packed fp32x2 helpers (Blackwell FFMA2 pipe) ----------------
__device__ __forceinline__ unsigned long long pack2_bcast(float v) {
    unsigned long long r;
    asm("mov.b64 %0, {%1, %1};" : "=l"(r) : "f"(v));
    return r;
}
__device__ __forceinline__ void unpack2(unsigned long long v, float& lo, float& hi) {
    asm("mov.b64 {%0, %1}, %2;" : "=f"(lo), "=f"(hi) : "l"(v));
}
__device__ __forceinline__ unsigned long long ffma2(unsigned long long a,
                                                    unsigned long long b,
                                                    unsigned long long c) {
    unsigned long long d;
    asm("fma.rn.f32x2 %0, %1, %2, %3;" : "=l"(d) : "l"(a), "l"(b), "l"(c));
    return d;
}

// ---------------- K0: zero scratch (graph-replay safe) ----------------
__global__ void zero_kernel() {
    const int total = KK * DD + KK + 2;
    for (int i = blockIdx.x * blockDim.x + threadIdx.x; i < total;
         i += gridDim.x * blockDim.x) {
        if (i < KK * DD)            g_dw[i] = 0.0f;
        else if (i < KK * DD + KK)  g_counts[i - KK * DD] = 0.0f;
        else                        g_scal[i - KK * DD - KK] = 0.0f;
    }
}

// ---------------- K1: row sums of squares (c2 for codebook, x2 for x) ----------------
__global__ void sumsq_kernel(const float* __restrict__ cb, const float* __restrict__ x) {
    int row  = (blockIdx.x * blockDim.x + threadIdx.x) >> 5;
    int lane = threadIdx.x & 31;
    if (row >= KK + NROWS) return;
    const float* p = (row < KK) ? (cb + (size_t)row * DD)
                                : (x + (size_t)(row - KK) * DD);
    float s = 0.0f;
    #pragma unroll
    for (int d = lane; d < DD; d += 32) { float v = p[d]; s += v * v; }
    #pragma unroll
    for (int o = 16; o > 0; o >>= 1) s += __shfl_xor_sync(0xFFFFFFFFu, s, o);
    if (lane == 0) {
        if (row < KK) g_c2[row] = s;
        else          g_x2[row - KK] = s;
    }
}

// ---------------- K2: fused GEMM + argmin (double-buffered, BK=8) ----------------
// grid = (128 m-tiles, 2 halves). Block: 128 x-rows x 2048 codes, BK=8.
// 256 threads = 16x16; each thread owns an 8x8 micro-tile as 8x4 f32x2 accums.
// Static smem 33.8 KB (under 48 KB cap); __launch_bounds__(256,2) -> 2 CTA/SM.
// Pipeline: issue LDGs for tile t+1, compute buf(t&1), store buf(t^1), ONE sync.
__global__ __launch_bounds__(256, 2) void argmin_kernel(const float* __restrict__ x,
                                                        const float* __restrict__ cb) {
    __shared__ float xs[2][8][132];   // [buf][k][m], padded rows (16B-aligned)
    __shared__ float cs[2][8][132];   // [buf][k][n]

    const int tid = threadIdx.x;
    const int tx = tid & 15, ty = tid >> 4;
    const int m0 = blockIdx.x * 128;
    const int half = blockIdx.y;
    const int nbase = half * NHALF;

    // per-thread load coords: each thread loads one float4 of one row per step
    const int lrow = tid >> 1;            // 0..127
    const int lkq  = (tid & 1) << 2;      // 0 or 4
    const float* xbase = x + (size_t)(m0 + lrow) * DD + lkq;

    float best[8];
    int   bidx[8];
    #pragma unroll
    for (int i = 0; i < 8; i++) { best[i] = 3.4e38f; bidx[i] = 0; }

    float x2v[8];
    #pragma unroll
    for (int i = 0; i < 8; i++) x2v[i] = g_x2[m0 + ty * 8 + i];

    for (int n0 = nbase; n0 < nbase + NHALF; n0 += 128) {
        const float* cbase = cb + (size_t)(n0 + lrow) * DD + lkq;

        unsigned long long acc2[8][4];
        #pragma unroll
        for (int i = 0; i < 8; i++)
            #pragma unroll
            for (int j = 0; j < 4; j++) acc2[i][j] = 0ull;

        // ---- prologue: load k0=0 tile into buf 0 ----
        float4 vx = *(const float4*)(xbase);
        float4 vc = *(const float4*)(cbase);
        xs[0][lkq + 0][lrow] = vx.x; xs[0][lkq + 1][lrow] = vx.y;
        xs[0][lkq + 2][lrow] = vx.z; xs[0][lkq + 3][lrow] = vx.w;
        cs[0][lkq + 0][lrow] = vc.x; cs[0][lkq + 1][lrow] = vc.y;
        cs[0][lkq + 2][lrow] = vc.z; cs[0][lkq + 3][lrow] = vc.w;
        __syncthreads();

        #pragma unroll 1
        for (int t = 0; t < 64; t++) {
            const int cur = t & 1;
            // issue LDGs for next tile (latency hidden by compute below)
            if (t < 63) {
                const int k0 = (t + 1) * 8;
                vx = *(const float4*)(xbase + k0);
                vc = *(const float4*)(cbase + k0);
            }
            // compute current buffer
            #pragma unroll
            for (int kk = 0; kk < 8; kk++) {
                const float4* ar = (const float4*)&xs[cur][kk][ty * 8];
                const unsigned long long* br =
                    (const unsigned long long*)&cs[cur][kk][tx * 8];
                float4 a0 = ar[0], a1 = ar[1];
                unsigned long long bp[4] = { br[0], br[1], br[2], br[3] };
                float av[8] = { a0.x, a0.y, a0.z, a0.w, a1.x, a1.y, a1.z, a1.w };
                #pragma unroll
                for (int i = 0; i < 8; i++) {
                    unsigned long long ap = pack2_bcast(av[i]);
                    #pragma unroll
                    for (int j = 0; j < 4; j++)
                        acc2[i][j] = ffma2(ap, bp[j], acc2[i][j]);
                }
            }
            // store next tile into the other buffer, then single barrier
            if (t < 63) {
                const int nb = cur ^ 1;
                xs[nb][lkq + 0][lrow] = vx.x; xs[nb][lkq + 1][lrow] = vx.y;
                xs[nb][lkq + 2][lrow] = vx.z; xs[nb][lkq + 3][lrow] = vx.w;
                cs[nb][lkq + 0][lrow] = vc.x; cs[nb][lkq + 1][lrow] = vc.y;
                cs[nb][lkq + 2][lrow] = vc.z; cs[nb][lkq + 3][lrow] = vc.w;
                __syncthreads();
            }
        }

        // Epilogue: d2 = (x2 - 2*xc) + c2, running argmin (n ascending => first-min)
        float c2v[8];
        #pragma unroll
        for (int j = 0; j < 8; j++) c2v[j] = g_c2[n0 + tx * 8 + j];
        #pragma unroll
        for (int i = 0; i < 8; i++) {
            #pragma unroll
            for (int j2 = 0; j2 < 4; j2++) {
                float lo, hi;
                unpack2(acc2[i][j2], lo, hi);
                int nl = n0 + tx * 8 + j2 * 2;
                float d0 = (x2v[i] - 2.0f * lo) + c2v[j2 * 2];
                float d1 = (x2v[i] - 2.0f * hi) + c2v[j2 * 2 + 1];
                if (d0 < best[i]) { best[i] = d0; bidx[i] = nl; }
                if (d1 < best[i]) { best[i] = d1; bidx[i] = nl + 1; }
            }
        }
        __syncthreads();   // protect buf 0 before next n-tile's prologue store
    }

    // Cross-lane argmin: the 16 tx lanes per row are consecutive lanes in this
    // warp (lane = (ty&1)*16 + tx). Butterfly with min + lower-index tiebreak.
    #pragma unroll
    for (int i = 0; i < 8; i++) {
        float v = best[i];
        int   id = bidx[i];
        #pragma unroll
        for (int o = 1; o < 16; o <<= 1) {
            float vp = __shfl_xor_sync(0xFFFFFFFFu, v, o);
            int   ip = __shfl_xor_sync(0xFFFFFFFFu, id, o);
            if (vp < v || (vp == v && ip < id)) { v = vp; id = ip; }
        }
        if (tx == 0) {
            g_pbv[half * NROWS + m0 + ty * 8 + i] = v;
            g_pbi[half * NROWS + m0 + ty * 8 + i] = id;
        }
    }
}

// ---------------- K2b: merge the two code-halves (tie -> lower half/index) ----------------
__global__ void reduce_kernel() {
    int r = blockIdx.x * blockDim.x + threadIdx.x;
    if (r >= NROWS) return;
    float v0 = g_pbv[r], v1 = g_pbv[NROWS + r];
    int   i0 = g_pbi[r], i1 = g_pbi[NROWS + r];
    // half-0 indices are strictly lower, so ties keep i0 (first-min semantics)
    g_idx[r] = (v1 < v0) ? i1 : i0;
}

// ---------------- K3: scatter-add counts and dw ----------------
__global__ void scatter_kernel(const float* __restrict__ x) {
    int w    = (blockIdx.x * blockDim.x + threadIdx.x) >> 5;
    int lane = threadIdx.x & 31;
    if (w >= NROWS) return;
    int idx = g_idx[w];
    if (lane == 0) atomicAdd(&g_counts[idx], 1.0f);
    const float* xr = x + (size_t)w * DD;
    float* dwr = g_dw + (size_t)idx * DD;
    #pragma unroll
    for (int d = lane; d < DD; d += 32) atomicAdd(&dwr[d], xr[d]);
}

// ---------------- K4: EMA cluster stats, bias, N ----------------
__global__ void stats_kernel(const float* __restrict__ hidden_cluster,
                             const float* __restrict__ count) {
    __shared__ float sred[1024];
    int t = threadIdx.x;
    float cnt1 = count[0] + 1.0f;
    float bias = 1.0f - exp2f(cnt1 * log2f(DECAYF));
    float local = 0.0f;
    for (int k = t; k < KK; k += 1024) {
        float hc = hidden_cluster[k] * DECAYF + (1.0f - DECAYF) * g_counts[k];
        float a  = hc / bias;
        g_avgc[k] = a;
        local += a;
    }
    sred[t] = local;
    __syncthreads();
    for (int s = 512; s > 0; s >>= 1) {
        if (t < s) sred[t] += sred[t + s];
        __syncthreads();
    }
    if (t == 0) { g_scal[0] = sred[0]; g_scal[2] = bias; }
}

// ---------------- K5: codebook_new ----------------
__global__ void cbnew_kernel(const float* __restrict__ hidden_dw) {
    int i = blockIdx.x * blockDim.x + threadIdx.x;  // grid covers KK*DD exactly
    if (i >= KK * DD) return;
    float N    = g_scal[0];
    float bias = g_scal[2];
    int   k    = i >> 9;
    float avgdw = (hidden_dw[i] * DECAYF + (1.0f - DECAYF) * g_dw[i]) / bias;
    float cc    = (g_avgc[k] + EPSF) / (N + 4096.0f * EPSF) * N;
    g_cbnew[i]  = avgdw / cc;
}

// ---------------- K6: gather quantized + loss partials + indices ----------------
__global__ void output_kernel(const float* __restrict__ x, float* __restrict__ out,
                              int out_size) {
    __shared__ float sred[128];
    int r = blockIdx.x;
    int t = threadIdx.x;
    int idx = g_idx[r];
    const float4* q4 = (const float4*)(g_cbnew + (size_t)idx * DD);
    const float4* x4 = (const float4*)(x + (size_t)r * DD);
    float4*       o4 = (float4*)(out + (size_t)r * DD);
    float4 q  = q4[t];
    float4 xv = x4[t];
    float4 o;
    o.x = xv.x + (q.x - xv.x);
    o.y = xv.y + (q.y - xv.y);
    o.z = xv.z + (q.z - xv.z);
    o.w = xv.w + (q.w - xv.w);
    float dx = xv.x - o.x, dy = xv.y - o.y, dz = xv.z - o.z, dw = xv.w - o.w;
    float local = dx * dx + dy * dy + dz * dz + dw * dw;
    o4[t] = o;
    sred[t] = local;
    __syncthreads();
    for (int s = 64; s > 0; s >>= 1) {
        if (t < s) sred[t] += sred[t + s];
        __syncthreads();
    }
    if (t == 0) {
        atomicAdd(&g_scal[1], sred[0]);
        if (out_size >= QELEMS + 1 + NROWS)
            out[QELEMS + 1 + r] = (float)idx;
    }
}

// ---------------- K7: finalize loss ----------------
__global__ void finalize_kernel(float* __restrict__ out, int out_size) {
    if (out_size > QELEMS)
        out[QELEMS] = 0.5f * (g_scal[1] / (float)QELEMS);
}

// ---------------- launch ----------------
extern "C" void kernel_launch(void* const* d_in, const int* in_sizes, int n_in,
                              void* d_out, int out_size) {
    const float* x              = (const float*)d_in[0];
    const float* codebook       = (const float*)d_in[1];
    const float* hidden_cluster = (const float*)d_in[2];
    const float* hidden_dw      = (const float*)d_in[3];
    const float* count          = (const float*)d_in[4];
    float* out = (float*)d_out;

    zero_kernel<<<2048, 1024>>>();
    sumsq_kernel<<<(KK + NROWS) / 8, 256>>>(codebook, x);
    argmin_kernel<<<dim3(NROWS / 128, 2), 256>>>(x, codebook);
    reduce_kernel<<<NROWS / 256, 256>>>();
    scatter_kernel<<<NROWS / 8, 256>>>(x);
    stats_kernel<<<1, 1024>>>(hidden_cluster, count);
    cbnew_kernel<<<(KK * DD) / 512, 512>>>(hidden_dw);
    output_kernel<<<NROWS, 128>>>(x, out, out_size);
    finalize_kernel<<<1, 1>>>(out, out_size);
}

// round 14
// speedup vs baseline: 2.3281x; 2.1346x over previous
#include <cuda_runtime.h>
#include <cuda_bf16.h>
#include <math.h>
#include <stdint.h>

// Problem constants
#define BB 8
#define LL 2048
#define DD 512
#define KK 4096
#define NROWS (BB * LL)          // 16384
#define QELEMS (NROWS * DD)      // 8388608
#define DECAYF 0.99f
#define EPSF 1e-5f
#define KL 1024                  // limb layout: [h(512) | m(512)]
#define NSPLIT 2                 // code-range split across blockIdx.y
#define SMEM_STAGE 65536         // 4 limb tiles x 16KB
#define MARGIN 1e-2f             // refine window (>> 4e-3 worst-case approx err)
#define CAND_CAP 64

// ---------------- scratch (device globals: no allocation allowed) ----------------
__device__ float g_c2[KK];
__device__ float g_x2[NROWS];
__device__ float g_counts[KK];
__device__ float g_dw[KK * DD];
__device__ float g_avgc[KK];
__device__ float g_cbnew[KK * DD];
__device__ float g_scal[4];                         // [0]=N, [1]=loss sum, [2]=bias
__device__ int   g_idx[NROWS];
__device__ float g_d2[(size_t)NROWS * KK];          // approx d2 (268 MB)
__device__ __nv_bfloat16 g_xe[(size_t)NROWS * KL];  // x limbs (33 MB)
__device__ __nv_bfloat16 g_ce[(size_t)KK * KL];     // codebook limbs (8.4 MB)

// ---------------- PTX helpers (portable sm_80+ ops only) ----------------
__device__ __forceinline__ uint32_t smem_u32(const void* p) {
    uint32_t a;
    asm("{ .reg .u64 t; cvta.to.shared.u64 t, %1; cvt.u32.u64 %0, t; }"
        : "=r"(a) : "l"(p));
    return a;
}
__device__ __forceinline__ void cp_async16(uint32_t dst, const void* src) {
    asm volatile("cp.async.cg.shared.global [%0], [%1], 16;"
                 :: "r"(dst), "l"(src) : "memory");
}
__device__ __forceinline__ void cp_commit_wait() {
    asm volatile("cp.async.commit_group;" ::: "memory");
    asm volatile("cp.async.wait_group 0;" ::: "memory");
}
__device__ __forceinline__ void ldsm_x4(uint32_t& r0, uint32_t& r1, uint32_t& r2,
                                        uint32_t& r3, uint32_t addr) {
    asm volatile("ldmatrix.sync.aligned.m8n8.x4.shared.b16 {%0,%1,%2,%3}, [%4];"
                 : "=r"(r0), "=r"(r1), "=r"(r2), "=r"(r3) : "r"(addr));
}
__device__ __forceinline__ void mma_bf16(float* c, const uint32_t* a,
                                         uint32_t b0, uint32_t b1) {
    asm volatile(
        "mma.sync.aligned.m16n8k16.row.col.f32.bf16.bf16.f32 "
        "{%0,%1,%2,%3}, {%4,%5,%6,%7}, {%8,%9}, {%0,%1,%2,%3};"
        : "+f"(c[0]), "+f"(c[1]), "+f"(c[2]), "+f"(c[3])
        : "r"(a[0]), "r"(a[1]), "r"(a[2]), "r"(a[3]), "r"(b0), "r"(b1));
}

// ---------------- K0: zero scratch ----------------
__global__ void zero_kernel() {
    const int total = KK * DD + KK + 2;
    for (int i = blockIdx.x * blockDim.x + threadIdx.x; i < total;
         i += gridDim.x * blockDim.x) {
        if (i < KK * DD)            g_dw[i] = 0.0f;
        else if (i < KK * DD + KK)  g_counts[i - KK * DD] = 0.0f;
        else                        g_scal[i - KK * DD - KK] = 0.0f;
    }
}

// ---------------- K1: bf16 2-limb Dekker decomposition ----------------
__global__ void decomp_kernel(const float* __restrict__ x, const float* __restrict__ cb) {
    const int total = (NROWS + KK) * DD;
    for (int i = blockIdx.x * blockDim.x + threadIdx.x; i < total;
         i += gridDim.x * blockDim.x) {
        bool isx = i < NROWS * DD;
        int  j   = isx ? i : i - NROWS * DD;
        float v  = isx ? x[j] : cb[j];
        __nv_bfloat16 h = __float2bfloat16(v);
        float r1 = v - __bfloat162float(h);           // exact (Sterbenz)
        __nv_bfloat16 m = __float2bfloat16(r1);
        int row = j >> 9, col = j & 511;
        size_t base = (size_t)row * KL + col;
        if (isx) { g_xe[base] = h; g_xe[base + 512] = m; }
        else     { g_ce[base] = h; g_ce[base + 512] = m; }
    }
}

// ---------------- K2: sums of squares (fp32 originals) ----------------
__global__ void sumsq_kernel(const float* __restrict__ cb, const float* __restrict__ x) {
    int row  = (blockIdx.x * blockDim.x + threadIdx.x) >> 5;
    int lane = threadIdx.x & 31;
    if (row >= KK + NROWS) return;
    const float* p = (row < KK) ? (cb + (size_t)row * DD)
                                : (x + (size_t)(row - KK) * DD);
    float s = 0.0f;
    #pragma unroll
    for (int d = lane; d < DD; d += 32) { float v = p[d]; s += v * v; }
    #pragma unroll
    for (int o = 16; o > 0; o >>= 1) s += __shfl_xor_sync(0xFFFFFFFFu, s, o);
    if (lane == 0) {
        if (row < KK) g_c2[row] = s;
        else          g_x2[row - KK] = s;
    }
}

// ---------------- K3: HMMA 2-limb GEMM, stores approx d2 ----------------
// grid (128 m-tiles, 2 n-splits), 256 threads = 8 warps (2m x 4n), warp m64n32.
// Per n-tile (128 codes): 8 stages of k64; per stage 3 limb pairs (hh, hm, mh).
__global__ __launch_bounds__(256, 2) void argmin_kernel() {
    extern __shared__ __align__(128) char dynsm[];
    const uint32_t sA = smem_u32(dynsm);            // 2 x 16KB A limb tiles
    const uint32_t sB = sA + 32768;                 // 2 x 16KB B limb tiles

    const int tid  = threadIdx.x;
    const int wid  = tid >> 5, lane = tid & 31;
    const int wm   = wid >> 2, wn = wid & 3;        // warp grid 2 x 4
    const int m0   = blockIdx.x * 128;
    const int nblk = blockIdx.y * (KK / NSPLIT);    // 2048-wide n range

    const int lrow = lane & 15, lhalf = lane >> 4;
    const int lr7  = lrow & 7;

    for (int nt = 0; nt < KK / NSPLIT / 128; nt++) {
        const int n0 = nblk + nt * 128;

        float acc[4][4][4];
        #pragma unroll
        for (int i = 0; i < 4; i++)
            #pragma unroll
            for (int j = 0; j < 4; j++)
                #pragma unroll
                for (int c = 0; c < 4; c++) acc[i][j][c] = 0.0f;

        for (int kb = 0; kb < 8; kb++) {            // k64 stages over D=512
            __syncthreads();                         // prior stage reads done
            #pragma unroll
            for (int s = 0; s < 16; s++) {
                int u   = s * 256 + tid;             // 0..4095
                int mat = u >> 10;                   // 0,1 = A h,m; 2,3 = B h,m
                int rem = u & 1023;
                int row = rem >> 3, q = rem & 7;
                uint32_t dst = (mat < 2 ? sA + mat * 16384
                                        : sB + (mat - 2) * 16384)
                             + row * 128 + ((q ^ (row & 7)) << 4);
                const __nv_bfloat16* src = (mat < 2)
                    ? g_xe + (size_t)(m0 + row) * KL + mat * 512 + kb * 64 + q * 8
                    : g_ce + (size_t)(n0 + row) * KL + (mat - 2) * 512 + kb * 64 + q * 8;
                cp_async16(dst, src);
            }
            cp_commit_wait();
            __syncthreads();

            #pragma unroll
            for (int k16 = 0; k16 < 4; k16++) {
                const int uA = ((k16 * 2 + lhalf) ^ lr7) << 4;
                uint32_t ah[4][4], am[4][4];
                #pragma unroll
                for (int im = 0; im < 4; im++) {
                    uint32_t base = (wm * 64 + im * 16 + lrow) * 128 + uA;
                    ldsm_x4(ah[im][0], ah[im][1], ah[im][2], ah[im][3], sA + base);
                    ldsm_x4(am[im][0], am[im][1], am[im][2], am[im][3],
                            sA + 16384 + base);
                }
                uint32_t bh[2][4], bm[2][4];
                #pragma unroll
                for (int nh = 0; nh < 2; nh++) {
                    uint32_t base = (wn * 32 + nh * 16 + lrow) * 128 + uA;
                    ldsm_x4(bh[nh][0], bh[nh][1], bh[nh][2], bh[nh][3], sB + base);
                    ldsm_x4(bm[nh][0], bm[nh][1], bm[nh][2], bm[nh][3],
                            sB + 16384 + base);
                }
                #pragma unroll
                for (int im = 0; im < 4; im++) {
                    // hh
                    mma_bf16(acc[im][0], ah[im], bh[0][0], bh[0][2]);
                    mma_bf16(acc[im][1], ah[im], bh[0][1], bh[0][3]);
                    mma_bf16(acc[im][2], ah[im], bh[1][0], bh[1][2]);
                    mma_bf16(acc[im][3], ah[im], bh[1][1], bh[1][3]);
                    // hm
                    mma_bf16(acc[im][0], ah[im], bm[0][0], bm[0][2]);
                    mma_bf16(acc[im][1], ah[im], bm[0][1], bm[0][3]);
                    mma_bf16(acc[im][2], ah[im], bm[1][0], bm[1][2]);
                    mma_bf16(acc[im][3], ah[im], bm[1][1], bm[1][3]);
                    // mh
                    mma_bf16(acc[im][0], am[im], bh[0][0], bh[0][2]);
                    mma_bf16(acc[im][1], am[im], bh[0][1], bh[0][3]);
                    mma_bf16(acc[im][2], am[im], bh[1][0], bh[1][2]);
                    mma_bf16(acc[im][3], am[im], bh[1][1], bh[1][3]);
                }
            }
        }

        // epilogue: store approx d2 = (x2 - 2*xc) + c2 for every (row, col)
        const int colb = n0 + wn * 32 + ((lane & 3) << 1);
        #pragma unroll
        for (int im = 0; im < 4; im++) {
            #pragma unroll
            for (int h = 0; h < 2; h++) {
                int row = m0 + wm * 64 + im * 16 + (lane >> 2) + h * 8;
                float x2v = g_x2[row];
                float* drow = g_d2 + (size_t)row * KK;
                #pragma unroll
                for (int j = 0; j < 4; j++) {
                    int c0 = colb + j * 8;
                    float2 dv;
                    dv.x = (x2v - 2.0f * acc[im][j][h * 2 + 0]) + g_c2[c0];
                    dv.y = (x2v - 2.0f * acc[im][j][h * 2 + 1]) + g_c2[c0 + 1];
                    *(float2*)(drow + c0) = dv;
                }
            }
        }
    }
}

// ---------------- K3b: exact fp32 refine within margin of approx min ----------------
// One warp per row: find approx min, collect codes within MARGIN, recompute
// those d2 in plain fp32 (correlated with reference), first-min tie-break.
__global__ void refine_kernel(const float* __restrict__ x, const float* __restrict__ cb) {
    __shared__ int scnt[8];
    __shared__ int scol[8][CAND_CAP];
    const int warp = threadIdx.x >> 5, lane = threadIdx.x & 31;
    const int r = blockIdx.x * 8 + warp;

    const float4* drow = (const float4*)(g_d2 + (size_t)r * KK);
    float mn = 3.4e38f;
    #pragma unroll 4
    for (int i = 0; i < 32; i++) {
        float4 v = drow[lane + i * 32];
        mn = fminf(mn, fminf(fminf(v.x, v.y), fminf(v.z, v.w)));
    }
    #pragma unroll
    for (int o = 16; o > 0; o >>= 1) mn = fminf(mn, __shfl_xor_sync(0xFFFFFFFFu, mn, o));
    const float thr = mn + MARGIN;

    if (lane == 0) scnt[warp] = 0;
    __syncwarp();
    #pragma unroll 4
    for (int i = 0; i < 32; i++) {
        float4 v = drow[lane + i * 32];
        int base = (lane + i * 32) * 4;
        #pragma unroll
        for (int c = 0; c < 4; c++) {
            float dv = (c == 0) ? v.x : (c == 1) ? v.y : (c == 2) ? v.z : v.w;
            if (dv <= thr) {
                int p = atomicAdd(&scnt[warp], 1);
                if (p < CAND_CAP) scol[warp][p] = base + c;
            }
        }
    }
    __syncwarp();
    int cnt = min(scnt[warp], CAND_CAP);

    const float* xr = x + (size_t)r * DD;
    float xl[16];
    #pragma unroll
    for (int t = 0; t < 16; t++) xl[t] = xr[lane * 16 + t];
    float x2v = g_x2[r];

    unsigned long long bkey = 0xFFFFFFFFFFFFFFFFull;
    for (int ci = 0; ci < cnt; ci++) {
        int col = scol[warp][ci];
        const float* cr = cb + (size_t)col * DD;
        float s = 0.0f;
        #pragma unroll
        for (int t = 0; t < 16; t++) s += xl[t] * cr[lane * 16 + t];
        #pragma unroll
        for (int o = 16; o > 0; o >>= 1) s += __shfl_xor_sync(0xFFFFFFFFu, s, o);
        float d2 = (x2v - 2.0f * s) + g_c2[col];
        unsigned long long k =
            ((unsigned long long)__float_as_uint(d2) << 32) | (unsigned)col;
        if (k < bkey) bkey = k;
    }
    if (lane == 0) g_idx[r] = (int)(bkey & 0xFFFFFFFFull);
}

// ---------------- K4: scatter-add counts and dw ----------------
__global__ void scatter_kernel(const float* __restrict__ x) {
    int w    = (blockIdx.x * blockDim.x + threadIdx.x) >> 5;
    int lane = threadIdx.x & 31;
    if (w >= NROWS) return;
    int idx = g_idx[w];
    if (lane == 0) atomicAdd(&g_counts[idx], 1.0f);
    const float* xr = x + (size_t)w * DD;
    float* dwr = g_dw + (size_t)idx * DD;
    #pragma unroll
    for (int d = lane; d < DD; d += 32) atomicAdd(&dwr[d], xr[d]);
}

// ---------------- K5: EMA cluster stats, bias, N ----------------
__global__ void stats_kernel(const float* __restrict__ hidden_cluster,
                             const float* __restrict__ count) {
    __shared__ float sred[1024];
    int t = threadIdx.x;
    float cnt1 = count[0] + 1.0f;
    float bias = 1.0f - exp2f(cnt1 * log2f(DECAYF));
    float local = 0.0f;
    for (int k = t; k < KK; k += 1024) {
        float hc = hidden_cluster[k] * DECAYF + (1.0f - DECAYF) * g_counts[k];
        float a  = hc / bias;
        g_avgc[k] = a;
        local += a;
    }
    sred[t] = local;
    __syncthreads();
    for (int s = 512; s > 0; s >>= 1) {
        if (t < s) sred[t] += sred[t + s];
        __syncthreads();
    }
    if (t == 0) { g_scal[0] = sred[0]; g_scal[2] = bias; }
}

// ---------------- K6: codebook_new ----------------
__global__ void cbnew_kernel(const float* __restrict__ hidden_dw) {
    int i = blockIdx.x * blockDim.x + threadIdx.x;
    if (i >= KK * DD) return;
    float N    = g_scal[0];
    float bias = g_scal[2];
    int   k    = i >> 9;
    float avgdw = (hidden_dw[i] * DECAYF + (1.0f - DECAYF) * g_dw[i]) / bias;
    float cc    = (g_avgc[k] + EPSF) / (N + 4096.0f * EPSF) * N;
    g_cbnew[i]  = avgdw / cc;
}

// ---------------- K7: gather quantized + loss partials + indices ----------------
__global__ void output_kernel(const float* __restrict__ x, float* __restrict__ out,
                              int out_size) {
    __shared__ float sred[128];
    int r = blockIdx.x;
    int t = threadIdx.x;
    int idx = g_idx[r];
    const float4* q4 = (const float4*)(g_cbnew + (size_t)idx * DD);
    const float4* x4 = (const float4*)(x + (size_t)r * DD);
    float4*       o4 = (float4*)(out + (size_t)r * DD);
    float4 q  = q4[t];
    float4 xv = x4[t];
    float4 o;
    o.x = xv.x + (q.x - xv.x);
    o.y = xv.y + (q.y - xv.y);
    o.z = xv.z + (q.z - xv.z);
    o.w = xv.w + (q.w - xv.w);
    float dx = xv.x - o.x, dy = xv.y - o.y, dz = xv.z - o.z, dw = xv.w - o.w;
    float local = dx * dx + dy * dy + dz * dz + dw * dw;
    o4[t] = o;
    sred[t] = local;
    __syncthreads();
    for (int s = 64; s > 0; s >>= 1) {
        if (t < s) sred[t] += sred[t + s];
        __syncthreads();
    }
    if (t == 0) {
        atomicAdd(&g_scal[1], sred[0]);
        if (out_size >= QELEMS + 1 + NROWS)
            out[QELEMS + 1 + r] = (float)idx;
    }
}

// ---------------- K8: finalize loss ----------------
__global__ void finalize_kernel(float* __restrict__ out, int out_size) {
    if (out_size > QELEMS)
        out[QELEMS] = 0.5f * (g_scal[1] / (float)QELEMS);
}

// ---------------- launch ----------------
extern "C" void kernel_launch(void* const* d_in, const int* in_sizes, int n_in,
                              void* d_out, int out_size) {
    const float* x              = (const float*)d_in[0];
    const float* codebook       = (const float*)d_in[1];
    const float* hidden_cluster = (const float*)d_in[2];
    const float* hidden_dw      = (const float*)d_in[3];
    const float* count          = (const float*)d_in[4];
    float* out = (float*)d_out;

    cudaFuncSetAttribute(argmin_kernel,
                         cudaFuncAttributeMaxDynamicSharedMemorySize, SMEM_STAGE);

    zero_kernel<<<2048, 1024>>>();
    decomp_kernel<<<4096, 512>>>(x, codebook);
    sumsq_kernel<<<(KK + NROWS) / 8, 256>>>(codebook, x);
    argmin_kernel<<<dim3(NROWS / 128, NSPLIT), 256, SMEM_STAGE>>>();
    refine_kernel<<<NROWS / 8, 256>>>(x, codebook);
    scatter_kernel<<<NROWS / 8, 256>>>(x);
    stats_kernel<<<1, 1024>>>(hidden_cluster, count);
    cbnew_kernel<<<(KK * DD) / 512, 512>>>(hidden_dw);
    output_kernel<<<NROWS, 128>>>(x, out, out_size);
    finalize_kernel<<<1, 1>>>(out, out_size);
}